// round 15
// baseline (speedup 1.0000x reference)
#include <cuda_runtime.h>
#include <math.h>
#include <stdint.h>

// PredictionHead: B=16, S=4096
// out = [start_prob (B*S) | end_prob (B*S) | start_pointer (B) | end_pointer (B)] as f32
//
// R15: ONE kernel, zero cross-CTA waits.
//  grid = 128 (16 rows x 8 chunks), 256 thr. Each CTA loads the FULL row
//  (L2-shared across its 8 sibling CTAs) and computes both softmax sums
//  redundantly (no communication). Windows/argmax are chunk-local via a
//  smem stash. Cross-chunk pointer argmax via packed u64 atomicMax +
//  fence/counter last-CTA-writes; scratch reset for graph-replay determinism.

#define S_LEN 4096
#define HALO  30
#define NCHK  8
#define CHUNK 512
#define NTHR  256
#define FULLM 0xffffffffu

__device__ unsigned long long g_packed[32];  // [row]=start, [16+row]=end
__device__ int g_cnt[16];

// inclusive warp scans: suffix-max (lane..31) and prefix-max (0..lane)
__device__ __forceinline__ void warp_scan_maxes(float v, int lid, float& suf, float& pre) {
    float s = v, p = v;
#pragma unroll
    for (int o = 1; o < 32; o <<= 1) {
        float td = __shfl_down_sync(FULLM, s, o);
        if (lid + o < 32) s = fmaxf(s, td);
        float tu = __shfl_up_sync(FULLM, p, o);
        if (lid >= o) p = fmaxf(p, tu);
    }
    suf = s; pre = p;
}
__device__ __forceinline__ float warp_prefix_max(float v, int lid) {
    float p = v;
#pragma unroll
    for (int o = 1; o < 32; o <<= 1) {
        float tu = __shfl_up_sync(FULLM, p, o);
        if (lid >= o) p = fmaxf(p, tu);
    }
    return p;
}

__global__ __launch_bounds__(NTHR, 1)
void ph_fused(const float* __restrict__ start_logits,
              const float* __restrict__ end_logits,
              float* __restrict__ out, int B)
{
    // spx[q] = sexp(base-30+q), q in [0,542): end window at li <-> spx[li..li+30]
    // epx[q] = eexp(base+q),    q in [0,542): start window at li <-> epx[li..li+30]
    __shared__ float spx[CHUNK + HALO];
    __shared__ float epx[CHUNK + HALO];
    __shared__ float prefA[CHUNK + HALO];
    __shared__ float prefE[CHUNK + HALO];
    __shared__ float redA[8], redB[8];
    __shared__ int   redIA[8], redIB[8];

    const int tid = threadIdx.x;
    const int wid = tid >> 5;
    const int lid = tid & 31;
    const int row   = blockIdx.x >> 3;
    const int chunk = blockIdx.x & 7;
    const int base  = chunk * CHUNK;
    const int vb    = base >> 2;          // own-chunk float4 range [vb, vb+128)

    const float4* s4 = reinterpret_cast<const float4*>(start_logits + (size_t)row * S_LEN);
    const float4* e4 = reinterpret_cast<const float4*>(end_logits   + (size_t)row * S_LEN);

    // pads where no halo exists (row edges)
    if (chunk == 0 && tid < HALO)        spx[tid] = 0.0f;
    if (chunk == NCHK - 1 && tid < HALO) epx[CHUNK + tid] = 0.0f;

    // ---- full-row load + exp + redundant sums + chunk-range stash ----
    float4 SV[4], EV[4];
    float ssum = 0.0f, esum = 0.0f;
#pragma unroll
    for (int q = 0; q < 4; q++) {
        int v = tid + NTHR * q;           // float4 index in [0,1024)
        float4 a = s4[v];
        float4 e = e4[v];
        a.x = __expf(a.x); a.y = __expf(a.y); a.z = __expf(a.z); a.w = __expf(a.w);
        e.x = __expf(e.x); e.y = __expf(e.y); e.z = __expf(e.z); e.w = __expf(e.w);
        SV[q] = a; EV[q] = e;
        ssum += (a.x + a.y) + (a.z + a.w);
        esum += (e.x + e.y) + (e.z + e.w);
        int j  = 4 * v;
        int ia = j - base + HALO;         // spx index of a.x
        if (ia >= -3 && ia < CHUNK + HALO) {
            if (ia >= 0 && ia < CHUNK + HALO)             spx[ia]     = a.x;
            if (ia + 1 >= 0 && ia + 1 < CHUNK + HALO)     spx[ia + 1] = a.y;
            if (ia + 2 >= 0 && ia + 2 < CHUNK + HALO)     spx[ia + 2] = a.z;
            if (ia + 3 >= 0 && ia + 3 < CHUNK + HALO)     spx[ia + 3] = a.w;
        }
        int ie = j - base;                // epx index of e.x
        if (ie >= -3 && ie < CHUNK + HALO) {
            if (ie >= 0 && ie < CHUNK + HALO)             epx[ie]     = e.x;
            if (ie + 1 >= 0 && ie + 1 < CHUNK + HALO)     epx[ie + 1] = e.y;
            if (ie + 2 >= 0 && ie + 2 < CHUNK + HALO)     epx[ie + 2] = e.z;
            if (ie + 3 >= 0 && ie + 3 < CHUNK + HALO)     epx[ie + 3] = e.w;
        }
    }

    // ---- intra-CTA sum reduce; totals broadcast via 8 direct LDS ----
#pragma unroll
    for (int o = 16; o; o >>= 1) {
        ssum += __shfl_xor_sync(FULLM, ssum, o);
        esum += __shfl_xor_sync(FULLM, esum, o);
    }
    if (lid == 0) { redA[wid] = ssum; redB[wid] = esum; }
    __syncthreads();   // publishes spx/epx + partial sums
    float Ss = 0.0f, Se = 0.0f;
#pragma unroll
    for (int w = 0; w < 8; w++) { Ss += redA[w]; Se += redB[w]; }
    const float sinv = 1.0f / Ss;
    const float einv = 1.0f / Se;

    // ---- block scans over the 542-element windows ----
    float sufA[2], sufE[2];
#pragma unroll
    for (int k = 0; k < 2; k++) {
        int li = k * NTHR + tid;
        float p;
        warp_scan_maxes(spx[li], lid, sufA[k], p);  prefA[li] = p;
        warp_scan_maxes(epx[li], lid, sufE[k], p);  prefE[li] = p;
    }
    if (wid == 0) {   // spx tail q=512..541
        float a = (lid < HALO) ? spx[CHUNK + lid] : 0.0f;
        float p = warp_prefix_max(a, lid);
        if (lid < HALO) prefA[CHUNK + lid] = p;
    }
    if (wid == 1) {   // epx tail
        float a = (lid < HALO) ? epx[CHUNK + lid] : 0.0f;
        float p = warp_prefix_max(a, lid);
        if (lid < HALO) prefE[CHUNK + lid] = p;
    }
    __syncthreads();

    // ---- window folds + local argmax (unnormalized; scale-invariant) ----
    float bS = -INFINITY, bE = -INFINITY;
    int   iS = 0, iE = 0;
#pragma unroll
    for (int k = 0; k < 2; k++) {
        int li = k * NTHR + tid;
        int gi = base + li;
        float we = (lid == 0) ? prefE[li + HALO] : (lid == 1) ? sufE[k]
                              : fmaxf(sufE[k], prefE[li + HALO]);
        float ws = (lid == 0) ? prefA[li + HALO] : (lid == 1) ? sufA[k]
                              : fmaxf(sufA[k], prefA[li + HALO]);
        float m = spx[HALO + li] * we;   // start candidate at gi
        float n = epx[li]        * ws;   // end candidate at gi
        if (m > bS) { bS = m; iS = gi; }   // ascending gi: strict > keeps first
        if (n > bE) { bE = n; iE = gi; }
    }

    // ---- normalized prob writes (own chunk only; exps live in registers) ----
    float4* so4 = reinterpret_cast<float4*>(out + (size_t)row * S_LEN);
    float4* eo4 = reinterpret_cast<float4*>(out + (size_t)B * S_LEN + (size_t)row * S_LEN);
#pragma unroll
    for (int q = 0; q < 4; q++) {
        int v = tid + NTHR * q;
        if (v >= vb && v < vb + CHUNK / 4) {
            float4 a = SV[q], e = EV[q];
            a.x *= sinv; a.y *= sinv; a.z *= sinv; a.w *= sinv;
            e.x *= einv; e.y *= einv; e.z *= einv; e.w *= einv;
            so4[v] = a;
            eo4[v] = e;
        }
    }

    // ---- block argmax reduce ----
#pragma unroll
    for (int o = 16; o; o >>= 1) {
        float ov = __shfl_xor_sync(FULLM, bS, o);
        int   oi = __shfl_xor_sync(FULLM, iS, o);
        if (ov > bS || (ov == bS && oi < iS)) { bS = ov; iS = oi; }
        ov = __shfl_xor_sync(FULLM, bE, o);
        oi = __shfl_xor_sync(FULLM, iE, o);
        if (ov > bE || (ov == bE && oi < iE)) { bE = ov; iE = oi; }
    }
    if (lid == 0) { redA[wid] = bS; redIA[wid] = iS; redB[wid] = bE; redIB[wid] = iE; }
    __syncthreads();
    if (wid == 0 && lid == 0) {
        float vS = redA[0]; int jS = redIA[0];
        float vE = redB[0]; int jE = redIB[0];
#pragma unroll
        for (int w = 1; w < 8; w++) {
            if (redA[w] > vS || (redA[w] == vS && redIA[w] < jS)) { vS = redA[w]; jS = redIA[w]; }
            if (redB[w] > vE || (redB[w] == vE && redIB[w] < jE)) { vE = redB[w]; jE = redIB[w]; }
        }
        // pack: positive-float bits are monotonic; ~index => lowest index wins ties
        unsigned long long ps = ((unsigned long long)__float_as_uint(vS) << 32)
                              | (unsigned long long)(FULLM - (uint32_t)jS);
        unsigned long long pe = ((unsigned long long)__float_as_uint(vE) << 32)
                              | (unsigned long long)(FULLM - (uint32_t)jE);
        atomicMax(&g_packed[row], ps);
        atomicMax(&g_packed[16 + row], pe);
        __threadfence();
        int old = atomicAdd(&g_cnt[row], 1);
        if (old == NCHK - 1) {   // last chunk CTA of this row: all maxes visible
            unsigned long long p1 = atomicMax(&g_packed[row], 0ULL);
            unsigned long long p2 = atomicMax(&g_packed[16 + row], 0ULL);
            float* ptr_out = out + 2 * (size_t)B * S_LEN;
            ptr_out[row]     = (float)(FULLM - (uint32_t)(p1 & FULLM));   // start_pointer
            ptr_out[B + row] = (float)(FULLM - (uint32_t)(p2 & FULLM));   // end_pointer
            // reset scratch for the next graph replay (deterministic)
            g_packed[row] = 0ULL;
            g_packed[16 + row] = 0ULL;
            g_cnt[row] = 0;
        }
    }
}

extern "C" void kernel_launch(void* const* d_in, const int* in_sizes, int n_in,
                              void* d_out, int out_size)
{
    const float* start_logits = (const float*)d_in[0];
    const float* end_logits   = (const float*)d_in[1];
    float* out = (float*)d_out;
    int B = in_sizes[0] / S_LEN;   // 16

    ph_fused<<<B * NCHK, NTHR>>>(start_logits, end_logits, out, B);
}

// round 16
// speedup vs baseline: 1.0072x; 1.0072x over previous
#include <cuda_runtime.h>
#include <math.h>
#include <stdint.h>

// PredictionHead: B=16, S=4096
// out = [start_prob (B*S) | end_prob (B*S) | start_pointer (B) | end_pointer (B)] as f32
//
// R16: R14's two-kernel split + Programmatic Dependent Launch.
//  Kernel A triggers PDL at entry -> kernel B launches immediately and burns its
//  launch/clock-ramp floor concurrently with A, blocked in
//  cudaGridDependencySynchronize() until A's memory is fully visible.
//  Scratch is plain-overwritten every call (graph-replay deterministic).

#define S_LEN 4096
#define HALO  30
#define NCHK  8
#define CHUNK 512
#define NTHR  256
#define FULLM 0xffffffffu

// scratch: [row*8+chunk]; candidates: [type*128 + row*8 + chunk] (type 0=start,1=end)
__device__ float g_sumS[128];
__device__ float g_sumE[128];
__device__ float g_candV[256];
__device__ int   g_candI[256];

// inclusive warp scans: suffix-max (lane..31) and prefix-max (0..lane)
__device__ __forceinline__ void warp_scan_maxes(float v, int lid, float& suf, float& pre) {
    float s = v, p = v;
#pragma unroll
    for (int o = 1; o < 32; o <<= 1) {
        float td = __shfl_down_sync(FULLM, s, o);
        if (lid + o < 32) s = fmaxf(s, td);
        float tu = __shfl_up_sync(FULLM, p, o);
        if (lid >= o) p = fmaxf(p, tu);
    }
    suf = s; pre = p;
}
__device__ __forceinline__ float warp_prefix_max(float v, int lid) {
    float p = v;
#pragma unroll
    for (int o = 1; o < 32; o <<= 1) {
        float tu = __shfl_up_sync(FULLM, p, o);
        if (lid >= o) p = fmaxf(p, tu);
    }
    return p;
}

// ---------------- Kernel A ----------------
__global__ __launch_bounds__(NTHR, 1)
void ph_partial(const float* __restrict__ start_logits,
                const float* __restrict__ end_logits,
                float* __restrict__ out, int B)
{
    // release the dependent launch immediately: B ramps while A works
    cudaTriggerProgrammaticLaunchCompletion();

    // A-space: spx[q] = sexp(base-30+q), q in [0,542). end window at li <-> q [li..li+30].
    // E-space: epx[q] = eexp(base+q),    q in [0,542). start window at li <-> q [li..li+30].
    __shared__ float spx[CHUNK + HALO + 32];
    __shared__ float epx[CHUNK + HALO + 32];
    __shared__ float prefA[CHUNK + HALO + 32];
    __shared__ float prefE[CHUNK + HALO + 32];
    __shared__ float redA[8], redB[8];
    __shared__ int   redIA[8], redIB[8];

    const int tid = threadIdx.x;
    const int wid = tid >> 5;
    const int lid = tid & 31;
    const int row   = blockIdx.x >> 3;
    const int chunk = blockIdx.x & 7;
    const int base  = chunk * CHUNK;

    const float* srow = start_logits + (size_t)row * S_LEN + base;
    const float* erow = end_logits   + (size_t)row * S_LEN + base;

    // own exps + smem + partial sums
    float sv[2], ev[2];
    float ssum = 0.0f, esum = 0.0f;
#pragma unroll
    for (int k = 0; k < 2; k++) {
        int li = k * NTHR + tid;
        sv[k] = __expf(srow[li]);
        ev[k] = __expf(erow[li]);
        ssum += sv[k];
        esum += ev[k];
        spx[HALO + li] = sv[k];
        epx[li]        = ev[k];
    }
    // halos straight from gmem (redundant with neighbor CTAs; no comms)
    if (tid < HALO) {
        float hs = 0.0f, he = 0.0f;
        if (chunk > 0)        hs = __expf(srow[tid - HALO]);       // sexp[base-30+tid]
        if (chunk < NCHK - 1) he = __expf(erow[CHUNK + tid]);      // eexp[base+512+tid]
        spx[tid] = hs;
        epx[CHUNK + tid] = he;
    }

    // intra-CTA sum reduce
#pragma unroll
    for (int o = 16; o; o >>= 1) {
        ssum += __shfl_xor_sync(FULLM, ssum, o);
        esum += __shfl_xor_sync(FULLM, esum, o);
    }
    if (lid == 0) { redA[wid] = ssum; redB[wid] = esum; }
    __syncthreads();   // also publishes spx/epx
    float totS = 0.0f, totE = 0.0f;
    if (wid == 0) {
        float a = redA[lid & 7], c = redB[lid & 7];
#pragma unroll
        for (int o = 4; o; o >>= 1) {
            a += __shfl_xor_sync(FULLM, a, o);
            c += __shfl_xor_sync(FULLM, c, o);
        }
        totS = a; totE = c;   // valid on lane 0
    }

    // block scans (thread scans q-block at its own li; tails by warps 0/1)
    float sufA[2], sufE[2];
#pragma unroll
    for (int k = 0; k < 2; k++) {
        int li = k * NTHR + tid;
        float p;
        float a = spx[li];
        warp_scan_maxes(a, lid, sufA[k], p);
        prefA[li] = p;
        warp_scan_maxes(ev[k], lid, sufE[k], p);   // epx[li] == ev[k]
        prefE[li] = p;
    }
    if (wid == 0) {   // A-space tail q=512..541 (own data: sexp[base+482..511])
        float a = (lid < HALO) ? spx[CHUNK + lid] : 0.0f;
        float p = warp_prefix_max(a, lid);
        if (lid < HALO) prefA[CHUNK + lid] = p;
    }
    if (wid == 1) {   // E-space tail (halo data)
        float a = (lid < HALO) ? epx[CHUNK + lid] : 0.0f;
        float p = warp_prefix_max(a, lid);
        if (lid < HALO) prefE[CHUNK + lid] = p;
    }
    __syncthreads();

    // window folds + local argmax (unnormalized; argmax is scale-invariant)
    float bS = -INFINITY, bE = -INFINITY;
    int   iS = 0, iE = 0;
#pragma unroll
    for (int k = 0; k < 2; k++) {
        int li = k * NTHR + tid;
        int gi = base + li;
        float we = (lid == 0) ? prefE[li + HALO] : (lid == 1) ? sufE[k]
                              : fmaxf(sufE[k], prefE[li + HALO]);
        float ws = (lid == 0) ? prefA[li + HALO] : (lid == 1) ? sufA[k]
                              : fmaxf(sufA[k], prefA[li + HALO]);
        float m = sv[k] * we;   // start candidate at gi
        float n = ev[k] * ws;   // end candidate at gi
        if (m > bS) { bS = m; iS = gi; }   // ascending gi: strict > keeps first
        if (n > bE) { bE = n; iE = gi; }
    }

    // unnormalized exps to out (kernel B scales in place)
    float* spo = out + (size_t)row * S_LEN + base;
    float* epo = out + (size_t)B * S_LEN + (size_t)row * S_LEN + base;
#pragma unroll
    for (int k = 0; k < 2; k++) {
        int li = k * NTHR + tid;
        spo[li] = sv[k];
        epo[li] = ev[k];
    }

    // argmax reduce -> scratch
#pragma unroll
    for (int o = 16; o; o >>= 1) {
        float ov = __shfl_xor_sync(FULLM, bS, o);
        int   oi = __shfl_xor_sync(FULLM, iS, o);
        if (ov > bS || (ov == bS && oi < iS)) { bS = ov; iS = oi; }
        ov = __shfl_xor_sync(FULLM, bE, o);
        oi = __shfl_xor_sync(FULLM, iE, o);
        if (ov > bE || (ov == bE && oi < iE)) { bE = ov; iE = oi; }
    }
    if (lid == 0) { redA[wid] = bS; redIA[wid] = iS; redB[wid] = bE; redIB[wid] = iE; }
    __syncthreads();
    if (wid == 0) {
        float vS = redA[lid & 7]; int jS = redIA[lid & 7];
        float vE = redB[lid & 7]; int jE = redIB[lid & 7];
#pragma unroll
        for (int o = 4; o; o >>= 1) {
            float ov = __shfl_xor_sync(FULLM, vS, o);
            int   oi = __shfl_xor_sync(FULLM, jS, o);
            if (ov > vS || (ov == vS && oi < jS)) { vS = ov; jS = oi; }
            ov = __shfl_xor_sync(FULLM, vE, o);
            oi = __shfl_xor_sync(FULLM, jE, o);
            if (ov > vE || (ov == vE && oi < jE)) { vE = ov; jE = oi; }
        }
        if (lid == 0) {
            int s = row * NCHK + chunk;
            g_sumS[s] = totS;
            g_sumE[s] = totE;
            g_candV[s]       = vS;  g_candI[s]       = jS;
            g_candV[128 + s] = vE;  g_candI[128 + s] = jE;
        }
    }
}

// ---------------- Kernel B (PDL dependent) ----------------
__global__ __launch_bounds__(NTHR, 1)
void ph_finalize(float* __restrict__ out, int B)
{
    const int tid = threadIdx.x;
    const int lid = tid & 31;
    const int c   = blockIdx.x;

    // address math before the dependency sync (overlaps A)
    int half = c >> 6;              // 0 = start probs, 1 = end probs
    int row  = (c & 63) >> 2;       // 4 CTAs per 4096-row
    float4* p = reinterpret_cast<float4*>(out) + (size_t)c * (1024 / 4) + tid;

    // block until ALL of kernel A's memory is visible
    cudaGridDependencySynchronize();

    // CTA 0: pointer reduction (256 threads = 16 rows x 2 types x 8 parts)
    if (c == 0) {
        int prow  = tid >> 4;
        int ptype = (tid >> 3) & 1;
        int part  = tid & 7;
        float v  = g_candV[ptype * 128 + prow * 8 + part];
        int   ix = g_candI[ptype * 128 + prow * 8 + part];
#pragma unroll
        for (int o = 4; o; o >>= 1) {   // xor-closed 8-groups within the warp
            float ov = __shfl_xor_sync(FULLM, v,  o);
            int   oi = __shfl_xor_sync(FULLM, ix, o);
            if (ov > v || (ov == v && oi < ix)) { v = ov; ix = oi; }
        }
        if ((tid & 7) == 0)
            out[2 * (size_t)B * S_LEN + ptype * B + prow] = (float)ix;
    }

    // in-place scaling: CTA c owns floats [c*1024, c*1024+1024)
    const float* sums = half ? g_sumE : g_sumS;
    float s = (lid < 8) ? sums[row * 8 + lid] : 0.0f;
#pragma unroll
    for (int o = 4; o; o >>= 1) s += __shfl_xor_sync(FULLM, s, o);
    float inv = 1.0f / __shfl_sync(FULLM, s, 0);

    float4 v = *p;
    v.x *= inv; v.y *= inv; v.z *= inv; v.w *= inv;
    *p = v;
}

extern "C" void kernel_launch(void* const* d_in, const int* in_sizes, int n_in,
                              void* d_out, int out_size)
{
    const float* start_logits = (const float*)d_in[0];
    const float* end_logits   = (const float*)d_in[1];
    float* out = (float*)d_out;
    int B = in_sizes[0] / S_LEN;   // 16

    ph_partial<<<B * NCHK, NTHR>>>(start_logits, end_logits, out, B);

    // dependent launch: allowed to start as soon as A triggers (A's entry),
    // serialized for memory by cudaGridDependencySynchronize() inside B.
    cudaLaunchConfig_t cfg = {};
    cfg.gridDim  = dim3(B * NCHK, 1, 1);
    cfg.blockDim = dim3(NTHR, 1, 1);
    cfg.stream   = 0;
    cudaLaunchAttribute attr[1];
    attr[0].id = cudaLaunchAttributeProgrammaticStreamSerialization;
    attr[0].val.programmaticStreamSerializationAllowed = 1;
    cfg.attrs    = attr;
    cfg.numAttrs = 1;
    cudaLaunchKernelEx(&cfg, ph_finalize, out, B);
}